// round 2
// baseline (speedup 1.0000x reference)
#include <cuda_runtime.h>
#include <cuda_bf16.h>
#include <math.h>

#define BB 4
#define TT 2048
#define DD 1024
#define HH 16
#define HD 64
#define MTOT (BB*TT)          // 8192
#define PAD 68                // smem row pitch (floats), 16B aligned

// ---------------------------------------------------------------------------
// Scratch (device globals: allocation inside kernel_launch is forbidden)
// ---------------------------------------------------------------------------
__device__ float g_q[MTOT * DD];
__device__ float g_k[MTOT * DD];
__device__ float g_v[MTOT * DD];
__device__ float g_attn[MTOT * DD];

// ---------------------------------------------------------------------------
// SGEMM:  C[M,N] = A[M,K] @ B[N,K]^T   (both row-major, K contiguous)
// 64x64 block tile, 16 k-slice, 256 threads, 4x4 microtile
// ---------------------------------------------------------------------------
__global__ __launch_bounds__(256) void gemm_nt_kernel(
    const float* __restrict__ A, const float* __restrict__ Bw,
    float* __restrict__ C, int M, int N, int K)
{
    __shared__ float As[16][65];
    __shared__ float Bs[16][65];

    const int tid = threadIdx.x;
    const int tx  = tid & 15;
    const int ty  = tid >> 4;
    const int bm  = blockIdx.y * 64;
    const int bn  = blockIdx.x * 64;

    const int lrow = tid >> 2;   // 0..63
    const int lq   = tid & 3;    // 0..3

    const float* Aptr = A  + (size_t)(bm + lrow) * K + lq * 4;
    const float* Bptr = Bw + (size_t)(bn + lrow) * K + lq * 4;

    float acc[4][4] = {};

    for (int kt = 0; kt < K; kt += 16) {
        float4 a4 = *(const float4*)(Aptr + kt);
        float4 b4 = *(const float4*)(Bptr + kt);
        As[lq*4+0][lrow] = a4.x;  As[lq*4+1][lrow] = a4.y;
        As[lq*4+2][lrow] = a4.z;  As[lq*4+3][lrow] = a4.w;
        Bs[lq*4+0][lrow] = b4.x;  Bs[lq*4+1][lrow] = b4.y;
        Bs[lq*4+2][lrow] = b4.z;  Bs[lq*4+3][lrow] = b4.w;
        __syncthreads();

        #pragma unroll
        for (int k = 0; k < 16; k++) {
            float ar[4], br[4];
            #pragma unroll
            for (int i = 0; i < 4; i++) ar[i] = As[k][ty*4 + i];
            #pragma unroll
            for (int j = 0; j < 4; j++) br[j] = Bs[k][tx*4 + j];
            #pragma unroll
            for (int i = 0; i < 4; i++)
                #pragma unroll
                for (int j = 0; j < 4; j++)
                    acc[i][j] = fmaf(ar[i], br[j], acc[i][j]);
        }
        __syncthreads();
    }

    #pragma unroll
    for (int i = 0; i < 4; i++)
        #pragma unroll
        for (int j = 0; j < 4; j++)
            C[(size_t)(bm + ty*4 + i) * N + bn + tx*4 + j] = acc[i][j];
}

// ---------------------------------------------------------------------------
// RoPE (in-place on Q and K). Each thread owns the pair (d, d+32) of one head.
// out[d]    = x[d]*cos[d]     - x[d+32]*sin[d]
// out[d+32] = x[d+32]*cos[d+32] + x[d]*sin[d+32]
// ---------------------------------------------------------------------------
__global__ __launch_bounds__(256) void rope_kernel(
    float* __restrict__ q, float* __restrict__ k,
    const float* __restrict__ cosb, const float* __restrict__ sinb)
{
    int idx = blockIdx.x * blockDim.x + threadIdx.x;   // B*T*H*32 threads
    if (idx >= BB * TT * HH * 32) return;
    int d  = idx & 31;
    int h  = (idx >> 5) & (HH - 1);
    int t  = (idx >> 9) & (TT - 1);
    int b  = idx >> 20;   // 32*16*2048 = 2^20

    size_t base = ((size_t)(b * TT + t)) * DD + h * HD;
    float c1 = cosb[t * HD + d],      s1 = sinb[t * HD + d];
    float c2 = cosb[t * HD + d + 32], s2 = sinb[t * HD + d + 32];

    float q1 = q[base + d], q2 = q[base + d + 32];
    q[base + d]      = q1 * c1 - q2 * s1;
    q[base + d + 32] = q2 * c2 + q1 * s2;

    float k1 = k[base + d], k2 = k[base + d + 32];
    k[base + d]      = k1 * c1 - k2 * s1;
    k[base + d + 32] = k2 * c2 + k1 * s2;
}

// ---------------------------------------------------------------------------
// Causal flash attention, fp32. One CTA = 64 query rows of one (b,h).
// Grid: (T/64, B*H). 256 threads, 4x4 microtile of the 64x64 S tile.
// smem: Qs[64][PAD], Kst[64][PAD] (K transposed: [d][key]), Vs[64][PAD],
//       Ps[64][PAD], m/l/f[64], red[64][17]
// ---------------------------------------------------------------------------
__global__ __launch_bounds__(256) void flash_attn_kernel(
    const float* __restrict__ Qg, const float* __restrict__ Kg,
    const float* __restrict__ Vg, float* __restrict__ Og)
{
    extern __shared__ float sm[];
    float* Qs   = sm;
    float* Kst  = Qs  + 64 * PAD;
    float* Vs   = Kst + 64 * PAD;
    float* Ps   = Vs  + 64 * PAD;
    float* mrow = Ps  + 64 * PAD;
    float* lrow = mrow + 64;
    float* frow = lrow + 64;
    float* red  = frow + 64;     // [64][17]

    const int tid = threadIdx.x;
    const int tx  = tid & 15;
    const int ty  = tid >> 4;
    const int qb  = blockIdx.x;
    const int bh  = blockIdx.y;
    const int b   = bh >> 4;
    const int h   = bh & 15;

    const size_t headoff = (size_t)(b * TT) * DD + (size_t)h * HD;
    const float scale = 0.125f;   // 1/sqrt(64)

    // Load Q tile [64 x 64]
    #pragma unroll
    for (int it = 0; it < 4; it++) {
        int idx = it * 256 + tid;         // 0..1023
        int row = idx >> 4;
        int c4  = idx & 15;
        float4 v4 = *(const float4*)&Qg[headoff + (size_t)(qb*64 + row) * DD + c4*4];
        *(float4*)&Qs[row * PAD + c4*4] = v4;
    }
    if (tid < 64) { mrow[tid] = -1e30f; lrow[tid] = 0.0f; }

    float acc[4][4] = {};
    __syncthreads();

    for (int kb = 0; kb <= qb; kb++) {
        // Load K (transposed into smem) and V tiles
        #pragma unroll
        for (int it = 0; it < 4; it++) {
            int idx = it * 256 + tid;
            int row = idx >> 4;
            int c4  = idx & 15;
            size_t goff = headoff + (size_t)(kb*64 + row) * DD + c4*4;
            float4 k4 = *(const float4*)&Kg[goff];
            Kst[(c4*4+0) * PAD + row] = k4.x;
            Kst[(c4*4+1) * PAD + row] = k4.y;
            Kst[(c4*4+2) * PAD + row] = k4.z;
            Kst[(c4*4+3) * PAD + row] = k4.w;
            float4 v4 = *(const float4*)&Vg[goff];
            *(float4*)&Vs[row * PAD + c4*4] = v4;
        }
        __syncthreads();

        // S = Q K^T (4x4 microtile per thread)
        float s[4][4] = {};
        #pragma unroll 4
        for (int d = 0; d < 64; d++) {
            float qr[4];
            #pragma unroll
            for (int i = 0; i < 4; i++) qr[i] = Qs[(ty*4 + i) * PAD + d];
            float4 kr = *(float4*)&Kst[d * PAD + tx*4];
            #pragma unroll
            for (int i = 0; i < 4; i++) {
                s[i][0] = fmaf(qr[i], kr.x, s[i][0]);
                s[i][1] = fmaf(qr[i], kr.y, s[i][1]);
                s[i][2] = fmaf(qr[i], kr.z, s[i][2]);
                s[i][3] = fmaf(qr[i], kr.w, s[i][3]);
            }
        }

        // scale + causal mask (only the diagonal block needs masking)
        if (kb == qb) {
            #pragma unroll
            for (int i = 0; i < 4; i++) {
                int qi = ty*4 + i;
                #pragma unroll
                for (int j = 0; j < 4; j++) {
                    int ki = tx*4 + j;
                    s[i][j] = (ki <= qi) ? s[i][j] * scale : -1e9f;
                }
            }
        } else {
            #pragma unroll
            for (int i = 0; i < 4; i++)
                #pragma unroll
                for (int j = 0; j < 4; j++) s[i][j] *= scale;
        }

        // row-max partial -> reduce across tx
        #pragma unroll
        for (int i = 0; i < 4; i++) {
            float pm = fmaxf(fmaxf(s[i][0], s[i][1]), fmaxf(s[i][2], s[i][3]));
            red[(ty*4 + i) * 17 + tx] = pm;
        }
        __syncthreads();
        if (tid < 64) {
            float mo = mrow[tid];
            float mn = mo;
            #pragma unroll
            for (int t2 = 0; t2 < 16; t2++) mn = fmaxf(mn, red[tid * 17 + t2]);
            mrow[tid] = mn;
            float f = __expf(mo - mn);
            frow[tid] = f;
            lrow[tid] *= f;
        }
        __syncthreads();

        // P = exp(S - m), partial row sums, rescale accumulators
        #pragma unroll
        for (int i = 0; i < 4; i++) {
            int r = ty*4 + i;
            float mn = mrow[r];
            float f  = frow[r];
            float rs = 0.0f;
            #pragma unroll
            for (int j = 0; j < 4; j++) {
                float p = __expf(s[i][j] - mn);
                Ps[r * PAD + tx*4 + j] = p;
                rs += p;
                acc[i][j] *= f;
            }
            red[r * 17 + tx] = rs;
        }
        __syncthreads();
        if (tid < 64) {
            float rs = 0.0f;
            #pragma unroll
            for (int t2 = 0; t2 < 16; t2++) rs += red[tid * 17 + t2];
            lrow[tid] += rs;
        }

        // O += P @ V
        #pragma unroll 4
        for (int kk = 0; kk < 64; kk++) {
            float pr[4];
            #pragma unroll
            for (int i = 0; i < 4; i++) pr[i] = Ps[(ty*4 + i) * PAD + kk];
            float4 vv = *(float4*)&Vs[kk * PAD + tx*4];
            #pragma unroll
            for (int i = 0; i < 4; i++) {
                acc[i][0] = fmaf(pr[i], vv.x, acc[i][0]);
                acc[i][1] = fmaf(pr[i], vv.y, acc[i][1]);
                acc[i][2] = fmaf(pr[i], vv.z, acc[i][2]);
                acc[i][3] = fmaf(pr[i], vv.w, acc[i][3]);
            }
        }
        __syncthreads();   // protects Kst/Vs/Ps for next iteration; also lrow update
    }

    // epilogue: divide by l, write to [B,T,H,Hd] layout
    #pragma unroll
    for (int i = 0; i < 4; i++) {
        int r  = ty*4 + i;
        float inv = 1.0f / lrow[r];
        int qi = qb*64 + r;
        #pragma unroll
        for (int j = 0; j < 4; j++)
            Og[headoff + (size_t)qi * DD + tx*4 + j] = acc[i][j] * inv;
    }
}

// ---------------------------------------------------------------------------
// kernel_launch
// inputs: x[B,T,D], cos[T,64], sin[T,64], w_q, w_k, w_v, w_o (all [D,D])
// ---------------------------------------------------------------------------
extern "C" void kernel_launch(void* const* d_in, const int* in_sizes, int n_in,
                              void* d_out, int out_size)
{
    const float* x    = (const float*)d_in[0];
    const float* cosb = (const float*)d_in[1];
    const float* sinb = (const float*)d_in[2];
    const float* w_q  = (const float*)d_in[3];
    const float* w_k  = (const float*)d_in[4];
    const float* w_v  = (const float*)d_in[5];
    const float* w_o  = (const float*)d_in[6];
    float* out = (float*)d_out;

    float *q, *k, *v, *attn;
    cudaGetSymbolAddress((void**)&q,    g_q);
    cudaGetSymbolAddress((void**)&k,    g_k);
    cudaGetSymbolAddress((void**)&v,    g_v);
    cudaGetSymbolAddress((void**)&attn, g_attn);

    const int smem_bytes = (4 * 64 * PAD + 3 * 64 + 64 * 17) * sizeof(float);
    cudaFuncSetAttribute(flash_attn_kernel,
                         cudaFuncAttributeMaxDynamicSharedMemorySize, smem_bytes);

    dim3 ggrid(DD / 64, MTOT / 64);   // (16, 128)
    gemm_nt_kernel<<<ggrid, 256>>>(x, w_q, q, MTOT, DD, DD);
    gemm_nt_kernel<<<ggrid, 256>>>(x, w_k, k, MTOT, DD, DD);
    gemm_nt_kernel<<<ggrid, 256>>>(x, w_v, v, MTOT, DD, DD);

    int rope_threads = BB * TT * HH * 32;
    rope_kernel<<<rope_threads / 256, 256>>>(q, k, cosb, sinb);

    flash_attn_kernel<<<dim3(TT / 64, BB * HH), 256, smem_bytes>>>(q, k, v, attn);

    gemm_nt_kernel<<<ggrid, 256>>>(attn, w_o, out, MTOT, DD, DD);
}

// round 3
// speedup vs baseline: 2.0010x; 2.0010x over previous
#include <cuda_runtime.h>
#include <cuda_bf16.h>
#include <math.h>

#define BB 4
#define TT 2048
#define DD 1024
#define HH 16
#define HD 64
#define MTOT (BB*TT)          // 8192
#define PAD 68                // flash smem pitch (floats)

// GEMM tiling
#define GPITCH 36             // smem row pitch in floats (144B, 16B aligned, conflict-free)
#define GTILE (128*GPITCH)    // floats per buffer per operand

// ---------------------------------------------------------------------------
// Scratch (device globals: allocation inside kernel_launch is forbidden)
// ---------------------------------------------------------------------------
__device__ float g_q[MTOT * DD];
__device__ float g_k[MTOT * DD];
__device__ float g_v[MTOT * DD];
__device__ float g_attn[MTOT * DD];

// ---------------------------------------------------------------------------
// helpers
// ---------------------------------------------------------------------------
__device__ __forceinline__ unsigned smem_u32(const void* p) {
    unsigned r;
    asm("{ .reg .u64 t; cvta.to.shared.u64 t, %1; cvt.u32.u64 %0, t; }"
        : "=r"(r) : "l"(p));
    return r;
}
__device__ __forceinline__ void cp_async16(unsigned s, const void* g) {
    asm volatile("cp.async.cg.shared.global [%0], [%1], 16;" :: "r"(s), "l"(g));
}
__device__ __forceinline__ void cp_commit() {
    asm volatile("cp.async.commit_group;");
}
__device__ __forceinline__ void cp_wait0() {
    asm volatile("cp.async.wait_group 0;");
}
// round-to-nearest tf32 (unbiased — plain truncation adds ~5e-4 systematic bias)
__device__ __forceinline__ unsigned f2tf32(float f) {
    unsigned u;
    asm("cvt.rna.tf32.f32 %0, %1;" : "=r"(u) : "f"(f));
    return u;
}
__device__ __forceinline__ void mma_tf32(float* c, const unsigned* a, const unsigned* b) {
    asm volatile(
        "mma.sync.aligned.m16n8k8.row.col.f32.tf32.tf32.f32 "
        "{%0,%1,%2,%3}, {%4,%5,%6,%7}, {%8,%9}, {%0,%1,%2,%3};"
        : "+f"(c[0]), "+f"(c[1]), "+f"(c[2]), "+f"(c[3])
        : "r"(a[0]), "r"(a[1]), "r"(a[2]), "r"(a[3]), "r"(b[0]), "r"(b[1]));
}

// ---------------------------------------------------------------------------
// TF32 tensor-core SGEMM:  C[M,N] = A[M,K] @ B[N,K]^T  (row-major, K contig)
// CTA tile 128x128, k-step 32, 256 threads = 8 warps (2 x 4), warp tile 64x32.
// cp.async double-buffered smem; fragments rounded with cvt.rna.
// M=8192, N=K=1024 fixed shapes for this problem.
// ---------------------------------------------------------------------------
__global__ __launch_bounds__(256) void gemm_tf32_kernel(
    const float* __restrict__ A, const float* __restrict__ Bw,
    float* __restrict__ C, int M, int N, int K)
{
    extern __shared__ float sm[];
    float* sA = sm;               // [2][128][GPITCH]
    float* sB = sm + 2 * GTILE;   // [2][128][GPITCH]

    const int tid  = threadIdx.x;
    const int lane = tid & 31;
    const int wid  = tid >> 5;
    const int wm   = wid & 1;     // 0..1  -> 64-row slice
    const int wn   = wid >> 1;    // 0..3  -> 32-col slice
    const int bm   = blockIdx.y * 128;
    const int bn   = blockIdx.x * 128;

    const int grp = lane >> 2;    // groupID 0..7
    const int tig = lane & 3;     // thread-in-group 0..3

    const unsigned uA = smem_u32(sA);
    const unsigned uB = smem_u32(sB);

    float acc[4][4][4] = {};      // [mi][ni][frag]

    const int NK = K / 32;

    // prefetch tile 0 into buffer 0
    {
        #pragma unroll
        for (int i = 0; i < 4; i++) {
            int idx = tid + 256 * i;          // 0..1023
            int row = idx >> 3;               // 0..127
            int c4  = idx & 7;                // 0..7 (float4 col)
            cp_async16(uA + (row * GPITCH + c4 * 4) * 4,
                       A + (size_t)(bm + row) * K + c4 * 4);
            cp_async16(uB + (row * GPITCH + c4 * 4) * 4,
                       Bw + (size_t)(bn + row) * K + c4 * 4);
        }
        cp_commit();
    }

    for (int kt = 0; kt < NK; kt++) {
        cp_wait0();
        __syncthreads();

        int nxt = kt + 1;
        if (nxt < NK) {
            int nb = nxt & 1;
            #pragma unroll
            for (int i = 0; i < 4; i++) {
                int idx = tid + 256 * i;
                int row = idx >> 3;
                int c4  = idx & 7;
                cp_async16(uA + (nb * GTILE + row * GPITCH + c4 * 4) * 4,
                           A + (size_t)(bm + row) * K + nxt * 32 + c4 * 4);
                cp_async16(uB + (nb * GTILE + row * GPITCH + c4 * 4) * 4,
                           Bw + (size_t)(bn + row) * K + nxt * 32 + c4 * 4);
            }
            cp_commit();
        }

        const float* As_ = sA + (kt & 1) * GTILE;
        const float* Bs_ = sB + (kt & 1) * GTILE;

        #pragma unroll
        for (int ks = 0; ks < 4; ks++) {
            int kc = ks * 8 + tig;
            unsigned a[4][4], b[4][2];
            #pragma unroll
            for (int mi = 0; mi < 4; mi++) {
                const float* p = As_ + (wm * 64 + mi * 16 + grp) * GPITCH + kc;
                a[mi][0] = f2tf32(p[0]);
                a[mi][1] = f2tf32(p[8 * GPITCH]);
                a[mi][2] = f2tf32(p[4]);
                a[mi][3] = f2tf32(p[8 * GPITCH + 4]);
            }
            #pragma unroll
            for (int ni = 0; ni < 4; ni++) {
                const float* p = Bs_ + (wn * 32 + ni * 8 + grp) * GPITCH + kc;
                b[ni][0] = f2tf32(p[0]);
                b[ni][1] = f2tf32(p[4]);
            }
            #pragma unroll
            for (int mi = 0; mi < 4; mi++)
                #pragma unroll
                for (int ni = 0; ni < 4; ni++)
                    mma_tf32(acc[mi][ni], a[mi], b[ni]);
        }
        // single sync per iter at loop top is enough: the buffer being
        // overwritten next is only touched two iterations out.
    }

    // epilogue: c0,c1 at (row, 2*tig), c2,c3 at (row+8, 2*tig)
    #pragma unroll
    for (int mi = 0; mi < 4; mi++) {
        int r0 = bm + wm * 64 + mi * 16 + grp;
        #pragma unroll
        for (int ni = 0; ni < 4; ni++) {
            int col = bn + wn * 32 + ni * 8 + tig * 2;
            float2 lo = make_float2(acc[mi][ni][0], acc[mi][ni][1]);
            float2 hi = make_float2(acc[mi][ni][2], acc[mi][ni][3]);
            *(float2*)&C[(size_t)r0 * N + col]       = lo;
            *(float2*)&C[(size_t)(r0 + 8) * N + col] = hi;
        }
    }
}

// ---------------------------------------------------------------------------
// RoPE (in-place on Q and K). Each thread owns the pair (d, d+32) of one head.
// ---------------------------------------------------------------------------
__global__ __launch_bounds__(256) void rope_kernel(
    float* __restrict__ q, float* __restrict__ k,
    const float* __restrict__ cosb, const float* __restrict__ sinb)
{
    int idx = blockIdx.x * blockDim.x + threadIdx.x;
    if (idx >= BB * TT * HH * 32) return;
    int d  = idx & 31;
    int h  = (idx >> 5) & (HH - 1);
    int t  = (idx >> 9) & (TT - 1);
    int b  = idx >> 20;

    size_t base = ((size_t)(b * TT + t)) * DD + h * HD;
    float c1 = cosb[t * HD + d],      s1 = sinb[t * HD + d];
    float c2 = cosb[t * HD + d + 32], s2 = sinb[t * HD + d + 32];

    float q1 = q[base + d], q2 = q[base + d + 32];
    q[base + d]      = q1 * c1 - q2 * s1;
    q[base + d + 32] = q2 * c2 + q1 * s2;

    float k1 = k[base + d], k2 = k[base + d + 32];
    k[base + d]      = k1 * c1 - k2 * s1;
    k[base + d + 32] = k2 * c2 + k1 * s2;
}

// ---------------------------------------------------------------------------
// Causal flash attention, fp32. One CTA = 64 query rows of one (b,h).
// ---------------------------------------------------------------------------
__global__ __launch_bounds__(256) void flash_attn_kernel(
    const float* __restrict__ Qg, const float* __restrict__ Kg,
    const float* __restrict__ Vg, float* __restrict__ Og)
{
    extern __shared__ float sm[];
    float* Qs   = sm;
    float* Kst  = Qs  + 64 * PAD;
    float* Vs   = Kst + 64 * PAD;
    float* Ps   = Vs  + 64 * PAD;
    float* mrow = Ps  + 64 * PAD;
    float* lrow = mrow + 64;
    float* frow = lrow + 64;
    float* red  = frow + 64;     // [64][17]

    const int tid = threadIdx.x;
    const int tx  = tid & 15;
    const int ty  = tid >> 4;
    const int qb  = blockIdx.x;
    const int bh  = blockIdx.y;
    const int b   = bh >> 4;
    const int h   = bh & 15;

    const size_t headoff = (size_t)(b * TT) * DD + (size_t)h * HD;
    const float scale = 0.125f;

    #pragma unroll
    for (int it = 0; it < 4; it++) {
        int idx = it * 256 + tid;
        int row = idx >> 4;
        int c4  = idx & 15;
        float4 v4 = *(const float4*)&Qg[headoff + (size_t)(qb*64 + row) * DD + c4*4];
        *(float4*)&Qs[row * PAD + c4*4] = v4;
    }
    if (tid < 64) { mrow[tid] = -1e30f; lrow[tid] = 0.0f; }

    float acc[4][4] = {};
    __syncthreads();

    for (int kb = 0; kb <= qb; kb++) {
        #pragma unroll
        for (int it = 0; it < 4; it++) {
            int idx = it * 256 + tid;
            int row = idx >> 4;
            int c4  = idx & 15;
            size_t goff = headoff + (size_t)(kb*64 + row) * DD + c4*4;
            float4 k4 = *(const float4*)&Kg[goff];
            Kst[(c4*4+0) * PAD + row] = k4.x;
            Kst[(c4*4+1) * PAD + row] = k4.y;
            Kst[(c4*4+2) * PAD + row] = k4.z;
            Kst[(c4*4+3) * PAD + row] = k4.w;
            float4 v4 = *(const float4*)&Vg[goff];
            *(float4*)&Vs[row * PAD + c4*4] = v4;
        }
        __syncthreads();

        float s[4][4] = {};
        #pragma unroll 4
        for (int d = 0; d < 64; d++) {
            float qr[4];
            #pragma unroll
            for (int i = 0; i < 4; i++) qr[i] = Qs[(ty*4 + i) * PAD + d];
            float4 kr = *(float4*)&Kst[d * PAD + tx*4];
            #pragma unroll
            for (int i = 0; i < 4; i++) {
                s[i][0] = fmaf(qr[i], kr.x, s[i][0]);
                s[i][1] = fmaf(qr[i], kr.y, s[i][1]);
                s[i][2] = fmaf(qr[i], kr.z, s[i][2]);
                s[i][3] = fmaf(qr[i], kr.w, s[i][3]);
            }
        }

        if (kb == qb) {
            #pragma unroll
            for (int i = 0; i < 4; i++) {
                int qi = ty*4 + i;
                #pragma unroll
                for (int j = 0; j < 4; j++) {
                    int ki = tx*4 + j;
                    s[i][j] = (ki <= qi) ? s[i][j] * scale : -1e9f;
                }
            }
        } else {
            #pragma unroll
            for (int i = 0; i < 4; i++)
                #pragma unroll
                for (int j = 0; j < 4; j++) s[i][j] *= scale;
        }

        #pragma unroll
        for (int i = 0; i < 4; i++) {
            float pm = fmaxf(fmaxf(s[i][0], s[i][1]), fmaxf(s[i][2], s[i][3]));
            red[(ty*4 + i) * 17 + tx] = pm;
        }
        __syncthreads();
        if (tid < 64) {
            float mo = mrow[tid];
            float mn = mo;
            #pragma unroll
            for (int t2 = 0; t2 < 16; t2++) mn = fmaxf(mn, red[tid * 17 + t2]);
            mrow[tid] = mn;
            float f = __expf(mo - mn);
            frow[tid] = f;
            lrow[tid] *= f;
        }
        __syncthreads();

        #pragma unroll
        for (int i = 0; i < 4; i++) {
            int r = ty*4 + i;
            float mn = mrow[r];
            float f  = frow[r];
            float rs = 0.0f;
            #pragma unroll
            for (int j = 0; j < 4; j++) {
                float p = __expf(s[i][j] - mn);
                Ps[r * PAD + tx*4 + j] = p;
                rs += p;
                acc[i][j] *= f;
            }
            red[r * 17 + tx] = rs;
        }
        __syncthreads();
        if (tid < 64) {
            float rs = 0.0f;
            #pragma unroll
            for (int t2 = 0; t2 < 16; t2++) rs += red[tid * 17 + t2];
            lrow[tid] += rs;
        }

        #pragma unroll 4
        for (int kk = 0; kk < 64; kk++) {
            float pr[4];
            #pragma unroll
            for (int i = 0; i < 4; i++) pr[i] = Ps[(ty*4 + i) * PAD + kk];
            float4 vv = *(float4*)&Vs[kk * PAD + tx*4];
            #pragma unroll
            for (int i = 0; i < 4; i++) {
                acc[i][0] = fmaf(pr[i], vv.x, acc[i][0]);
                acc[i][1] = fmaf(pr[i], vv.y, acc[i][1]);
                acc[i][2] = fmaf(pr[i], vv.z, acc[i][2]);
                acc[i][3] = fmaf(pr[i], vv.w, acc[i][3]);
            }
        }
        __syncthreads();
    }

    #pragma unroll
    for (int i = 0; i < 4; i++) {
        int r  = ty*4 + i;
        float inv = 1.0f / lrow[r];
        int qi = qb*64 + r;
        #pragma unroll
        for (int j = 0; j < 4; j++)
            Og[headoff + (size_t)qi * DD + tx*4 + j] = acc[i][j] * inv;
    }
}

// ---------------------------------------------------------------------------
// kernel_launch
// ---------------------------------------------------------------------------
extern "C" void kernel_launch(void* const* d_in, const int* in_sizes, int n_in,
                              void* d_out, int out_size)
{
    const float* x    = (const float*)d_in[0];
    const float* cosb = (const float*)d_in[1];
    const float* sinb = (const float*)d_in[2];
    const float* w_q  = (const float*)d_in[3];
    const float* w_k  = (const float*)d_in[4];
    const float* w_v  = (const float*)d_in[5];
    const float* w_o  = (const float*)d_in[6];
    float* out = (float*)d_out;

    float *q, *k, *v, *attn;
    cudaGetSymbolAddress((void**)&q,    g_q);
    cudaGetSymbolAddress((void**)&k,    g_k);
    cudaGetSymbolAddress((void**)&v,    g_v);
    cudaGetSymbolAddress((void**)&attn, g_attn);

    const int fa_smem = (4 * 64 * PAD + 3 * 64 + 64 * 17) * sizeof(float);
    cudaFuncSetAttribute(flash_attn_kernel,
                         cudaFuncAttributeMaxDynamicSharedMemorySize, fa_smem);

    const int gm_smem = 4 * GTILE * sizeof(float);   // 73728 bytes
    cudaFuncSetAttribute(gemm_tf32_kernel,
                         cudaFuncAttributeMaxDynamicSharedMemorySize, gm_smem);

    dim3 ggrid(DD / 128, MTOT / 128);   // (8, 64)
    gemm_tf32_kernel<<<ggrid, 256, gm_smem>>>(x, w_q, q, MTOT, DD, DD);
    gemm_tf32_kernel<<<ggrid, 256, gm_smem>>>(x, w_k, k, MTOT, DD, DD);
    gemm_tf32_kernel<<<ggrid, 256, gm_smem>>>(x, w_v, v, MTOT, DD, DD);

    int rope_threads = BB * TT * HH * 32;
    rope_kernel<<<rope_threads / 256, 256>>>(q, k, cosb, sinb);

    flash_attn_kernel<<<dim3(TT / 64, BB * HH), 256, fa_smem>>>(q, k, v, attn);

    gemm_tf32_kernel<<<ggrid, 256, gm_smem>>>(attn, w_o, out, MTOT, DD, DD);
}

// round 4
// speedup vs baseline: 3.4044x; 1.7014x over previous
#include <cuda_runtime.h>
#include <cuda_bf16.h>
#include <math.h>

#define BB 4
#define TT 2048
#define DD 1024
#define HH 16
#define HD 64
#define MTOT (BB*TT)          // 8192

// GEMM tiling
#define GPITCH 36
#define GTILE (128*GPITCH)

// flash tiling
#define KPITCH 68             // Ks pitch (floats): b-frag banks (4*grp+tig) distinct
#define VPITCH 72             // Vs pitch: b-frag banks (8*tig+grp) distinct
#define PPITCH 68             // Ps pitch: a-frag banks (4*grp+tig) distinct
#define KS_BUF (64*KPITCH)
#define VS_BUF (64*VPITCH)

__device__ float g_q[MTOT * DD];
__device__ float g_k[MTOT * DD];
__device__ float g_v[MTOT * DD];
__device__ float g_attn[MTOT * DD];

// ---------------------------------------------------------------------------
__device__ __forceinline__ unsigned smem_u32(const void* p) {
    unsigned r;
    asm("{ .reg .u64 t; cvta.to.shared.u64 t, %1; cvt.u32.u64 %0, t; }"
        : "=r"(r) : "l"(p));
    return r;
}
__device__ __forceinline__ void cp_async16(unsigned s, const void* g) {
    asm volatile("cp.async.cg.shared.global [%0], [%1], 16;" :: "r"(s), "l"(g));
}
__device__ __forceinline__ void cp_commit() { asm volatile("cp.async.commit_group;"); }
__device__ __forceinline__ void cp_wait0()  { asm volatile("cp.async.wait_group 0;"); }
__device__ __forceinline__ unsigned f2tf32(float f) {
    unsigned u;
    asm("cvt.rna.tf32.f32 %0, %1;" : "=r"(u) : "f"(f));
    return u;
}
__device__ __forceinline__ void mma_tf32(float* c, const unsigned* a, const unsigned* b) {
    asm volatile(
        "mma.sync.aligned.m16n8k8.row.col.f32.tf32.tf32.f32 "
        "{%0,%1,%2,%3}, {%4,%5,%6,%7}, {%8,%9}, {%0,%1,%2,%3};"
        : "+f"(c[0]), "+f"(c[1]), "+f"(c[2]), "+f"(c[3])
        : "r"(a[0]), "r"(a[1]), "r"(a[2]), "r"(a[3]), "r"(b[0]), "r"(b[1]));
}

// ---------------------------------------------------------------------------
// TF32 tensor-core GEMM:  C[M,N] = A[M,K] @ B[N,K]^T   (unchanged from R2)
// ---------------------------------------------------------------------------
__global__ __launch_bounds__(256) void gemm_tf32_kernel(
    const float* __restrict__ A, const float* __restrict__ Bw,
    float* __restrict__ C, int M, int N, int K)
{
    extern __shared__ float sm[];
    float* sA = sm;
    float* sB = sm + 2 * GTILE;

    const int tid  = threadIdx.x;
    const int lane = tid & 31;
    const int wid  = tid >> 5;
    const int wm   = wid & 1;
    const int wn   = wid >> 1;
    const int bm   = blockIdx.y * 128;
    const int bn   = blockIdx.x * 128;
    const int grp  = lane >> 2;
    const int tig  = lane & 3;

    const unsigned uA = smem_u32(sA);
    const unsigned uB = smem_u32(sB);

    float acc[4][4][4] = {};
    const int NK = K / 32;

    {
        #pragma unroll
        for (int i = 0; i < 4; i++) {
            int idx = tid + 256 * i;
            int row = idx >> 3;
            int c4  = idx & 7;
            cp_async16(uA + (row * GPITCH + c4 * 4) * 4,
                       A + (size_t)(bm + row) * K + c4 * 4);
            cp_async16(uB + (row * GPITCH + c4 * 4) * 4,
                       Bw + (size_t)(bn + row) * K + c4 * 4);
        }
        cp_commit();
    }

    for (int kt = 0; kt < NK; kt++) {
        cp_wait0();
        __syncthreads();

        int nxt = kt + 1;
        if (nxt < NK) {
            int nb = nxt & 1;
            #pragma unroll
            for (int i = 0; i < 4; i++) {
                int idx = tid + 256 * i;
                int row = idx >> 3;
                int c4  = idx & 7;
                cp_async16(uA + (nb * GTILE + row * GPITCH + c4 * 4) * 4,
                           A + (size_t)(bm + row) * K + nxt * 32 + c4 * 4);
                cp_async16(uB + (nb * GTILE + row * GPITCH + c4 * 4) * 4,
                           Bw + (size_t)(bn + row) * K + nxt * 32 + c4 * 4);
            }
            cp_commit();
        }

        const float* As_ = sA + (kt & 1) * GTILE;
        const float* Bs_ = sB + (kt & 1) * GTILE;

        #pragma unroll
        for (int ks = 0; ks < 4; ks++) {
            int kc = ks * 8 + tig;
            unsigned a[4][4], b[4][2];
            #pragma unroll
            for (int mi = 0; mi < 4; mi++) {
                const float* p = As_ + (wm * 64 + mi * 16 + grp) * GPITCH + kc;
                a[mi][0] = f2tf32(p[0]);
                a[mi][1] = f2tf32(p[8 * GPITCH]);
                a[mi][2] = f2tf32(p[4]);
                a[mi][3] = f2tf32(p[8 * GPITCH + 4]);
            }
            #pragma unroll
            for (int ni = 0; ni < 4; ni++) {
                const float* p = Bs_ + (wn * 32 + ni * 8 + grp) * GPITCH + kc;
                b[ni][0] = f2tf32(p[0]);
                b[ni][1] = f2tf32(p[4]);
            }
            #pragma unroll
            for (int mi = 0; mi < 4; mi++)
                #pragma unroll
                for (int ni = 0; ni < 4; ni++)
                    mma_tf32(acc[mi][ni], a[mi], b[ni]);
        }
    }

    #pragma unroll
    for (int mi = 0; mi < 4; mi++) {
        int r0 = bm + wm * 64 + mi * 16 + grp;
        #pragma unroll
        for (int ni = 0; ni < 4; ni++) {
            int col = bn + wn * 32 + ni * 8 + tig * 2;
            *(float2*)&C[(size_t)r0 * N + col]       = make_float2(acc[mi][ni][0], acc[mi][ni][1]);
            *(float2*)&C[(size_t)(r0 + 8) * N + col] = make_float2(acc[mi][ni][2], acc[mi][ni][3]);
        }
    }
}

// ---------------------------------------------------------------------------
// RoPE (in-place on Q and K)
// ---------------------------------------------------------------------------
__global__ __launch_bounds__(256) void rope_kernel(
    float* __restrict__ q, float* __restrict__ k,
    const float* __restrict__ cosb, const float* __restrict__ sinb)
{
    int idx = blockIdx.x * blockDim.x + threadIdx.x;
    if (idx >= BB * TT * HH * 32) return;
    int d  = idx & 31;
    int h  = (idx >> 5) & (HH - 1);
    int t  = (idx >> 9) & (TT - 1);
    int b  = idx >> 20;

    size_t base = ((size_t)(b * TT + t)) * DD + h * HD;
    float c1 = cosb[t * HD + d],      s1 = sinb[t * HD + d];
    float c2 = cosb[t * HD + d + 32], s2 = sinb[t * HD + d + 32];

    float q1 = q[base + d], q2 = q[base + d + 32];
    q[base + d]      = q1 * c1 - q2 * s1;
    q[base + d + 32] = q2 * c2 + q1 * s2;

    float k1 = k[base + d], k2 = k[base + d + 32];
    k[base + d]      = k1 * c1 - k2 * s1;
    k[base + d + 32] = k2 * c2 + k1 * s2;
}

// ---------------------------------------------------------------------------
// Tensor-core causal flash attention (tf32 mma).
// CTA: 128 q-rows of one (b,h); 8 warps, warp w owns rows w*16..w*16+15.
// Grid: (T/128, B*H). K/V tiles of 64 keys, cp.async double-buffered.
// smem: Ks[2][64][KPITCH], Vs[2][64][VPITCH], Ps[128][PPITCH]
// ---------------------------------------------------------------------------
__global__ __launch_bounds__(256) void flash_attn_tc_kernel(
    const float* __restrict__ Qg, const float* __restrict__ Kg,
    const float* __restrict__ Vg, float* __restrict__ Og)
{
    extern __shared__ float sm[];
    float* Ks = sm;                       // 2 buffers
    float* Vs = Ks + 2 * KS_BUF;          // 2 buffers
    float* Ps = Vs + 2 * VS_BUF;          // [128][PPITCH]

    const int tid  = threadIdx.x;
    const int lane = tid & 31;
    const int w    = tid >> 5;            // warp 0..7
    const int grp  = lane >> 2;           // 0..7
    const int tig  = lane & 3;            // 0..3
    const int qb   = blockIdx.x;          // q tile (128 rows)
    const int bh   = blockIdx.y;
    const int b    = bh >> 4;
    const int h    = bh & 15;

    const size_t headoff = (size_t)(b * TT) * DD + (size_t)h * HD;
    const float scale = 0.125f;
    const unsigned uK = smem_u32(Ks);
    const unsigned uV = smem_u32(Vs);

    // ---- stage Q tile [128 x 64] into Ps, then convert to register frags ----
    #pragma unroll
    for (int i = 0; i < 8; i++) {
        int idx = i * 256 + tid;          // 0..2047
        int row = idx >> 4;               // 0..127
        int c4  = idx & 15;               // 0..15
        float4 v4 = *(const float4*)&Qg[headoff + (size_t)(qb*128 + row) * DD + c4*4];
        *(float4*)&Ps[row * PPITCH + c4*4] = v4;
    }
    __syncthreads();

    unsigned qa[8][4];                    // Q frags: 8 k-steps (d-dim)
    {
        const float* p0 = Ps + (w * 16 + grp) * PPITCH;
        #pragma unroll
        for (int ks = 0; ks < 8; ks++) {
            int kc = ks * 8 + tig;
            qa[ks][0] = f2tf32(p0[kc]);
            qa[ks][1] = f2tf32(p0[8 * PPITCH + kc]);
            qa[ks][2] = f2tf32(p0[kc + 4]);
            qa[ks][3] = f2tf32(p0[8 * PPITCH + kc + 4]);
        }
    }
    // each warp only writes its own Ps rows afterwards -> no block sync needed
    __syncwarp();

    float acc_o[8][4] = {};               // O accum: 8 d-tiles
    float m_lo = -1e30f, m_hi = -1e30f;
    float l_lo = 0.0f,   l_hi = 0.0f;

    const int kb_max = 2 * qb + 1;
    const int q_lo = qb * 128 + w * 16 + grp;    // row of c0/c1
    const int q_hi = q_lo + 8;                   // row of c2/c3

    // prefetch kb=0
    {
        #pragma unroll
        for (int i = 0; i < 8; i++) {
            int idx = i * 256 + tid;      // 0..2047: first 1024 K, rest V
            int row = (idx >> 4) & 63;
            int c4  = idx & 15;
            size_t goff = headoff + (size_t)row * DD + c4 * 4;
            if (idx < 1024)
                cp_async16(uK + (row * KPITCH + c4 * 4) * 4, Kg + goff);
            else
                cp_async16(uV + (row * VPITCH + c4 * 4) * 4, Vg + goff);
        }
        cp_commit();
    }

    for (int kb = 0; kb <= kb_max; kb++) {
        cp_wait0();
        __syncthreads();

        if (kb < kb_max) {
            int nb = (kb + 1) & 1;
            #pragma unroll
            for (int i = 0; i < 8; i++) {
                int idx = i * 256 + tid;
                int row = (idx >> 4) & 63;
                int c4  = idx & 15;
                size_t goff = headoff + (size_t)((kb+1)*64 + row) * DD + c4 * 4;
                if (idx < 1024)
                    cp_async16(uK + (nb * KS_BUF + row * KPITCH + c4 * 4) * 4, Kg + goff);
                else
                    cp_async16(uV + (nb * VS_BUF + row * VPITCH + c4 * 4) * 4, Vg + goff);
            }
            cp_commit();
        }

        const float* Ks_ = Ks + (kb & 1) * KS_BUF;
        const float* Vs_ = Vs + (kb & 1) * VS_BUF;

        // ---- S = Q @ K^T : acc_s[ni] covers keys ni*8..ni*8+7 ----
        float acc_s[8][4] = {};
        #pragma unroll
        for (int ks = 0; ks < 8; ks++) {
            int kc = ks * 8 + tig;
            unsigned bfr[8][2];
            #pragma unroll
            for (int ni = 0; ni < 8; ni++) {
                const float* p = Ks_ + (ni * 8 + grp) * KPITCH + kc;
                bfr[ni][0] = f2tf32(p[0]);
                bfr[ni][1] = f2tf32(p[4]);
            }
            #pragma unroll
            for (int ni = 0; ni < 8; ni++)
                mma_tf32(acc_s[ni], qa[ks], bfr[ni]);
        }

        // ---- scale + causal mask ----
        const bool diag = (kb >= 2 * qb);
        #pragma unroll
        for (int ni = 0; ni < 8; ni++) {
            int k0 = kb * 64 + ni * 8 + 2 * tig;
            if (diag) {
                acc_s[ni][0] = (k0     <= q_lo) ? acc_s[ni][0] * scale : -1e30f;
                acc_s[ni][1] = (k0 + 1 <= q_lo) ? acc_s[ni][1] * scale : -1e30f;
                acc_s[ni][2] = (k0     <= q_hi) ? acc_s[ni][2] * scale : -1e30f;
                acc_s[ni][3] = (k0 + 1 <= q_hi) ? acc_s[ni][3] * scale : -1e30f;
            } else {
                acc_s[ni][0] *= scale; acc_s[ni][1] *= scale;
                acc_s[ni][2] *= scale; acc_s[ni][3] *= scale;
            }
        }

        // ---- online softmax: row max over 4 tig lanes ----
        float tm_lo = -1e30f, tm_hi = -1e30f;
        #pragma unroll
        for (int ni = 0; ni < 8; ni++) {
            tm_lo = fmaxf(tm_lo, fmaxf(acc_s[ni][0], acc_s[ni][1]));
            tm_hi = fmaxf(tm_hi, fmaxf(acc_s[ni][2], acc_s[ni][3]));
        }
        tm_lo = fmaxf(tm_lo, __shfl_xor_sync(0xffffffffu, tm_lo, 1));
        tm_lo = fmaxf(tm_lo, __shfl_xor_sync(0xffffffffu, tm_lo, 2));
        tm_hi = fmaxf(tm_hi, __shfl_xor_sync(0xffffffffu, tm_hi, 1));
        tm_hi = fmaxf(tm_hi, __shfl_xor_sync(0xffffffffu, tm_hi, 2));

        float mn_lo = fmaxf(m_lo, tm_lo);
        float mn_hi = fmaxf(m_hi, tm_hi);
        float f_lo = __expf(m_lo - mn_lo);
        float f_hi = __expf(m_hi - mn_hi);
        m_lo = mn_lo; m_hi = mn_hi;

        // ---- P = exp(S - m), write own slab of Ps, partial row sums ----
        float rs_lo = 0.0f, rs_hi = 0.0f;
        float* Pw = Ps + (w * 16 + grp) * PPITCH;
        #pragma unroll
        for (int ni = 0; ni < 8; ni++) {
            float p0 = __expf(acc_s[ni][0] - mn_lo);
            float p1 = __expf(acc_s[ni][1] - mn_lo);
            float p2 = __expf(acc_s[ni][2] - mn_hi);
            float p3 = __expf(acc_s[ni][3] - mn_hi);
            rs_lo += p0 + p1;
            rs_hi += p2 + p3;
            *(float2*)&Pw[ni * 8 + 2 * tig]              = make_float2(p0, p1);
            *(float2*)&Pw[8 * PPITCH + ni * 8 + 2 * tig] = make_float2(p2, p3);
        }
        rs_lo += __shfl_xor_sync(0xffffffffu, rs_lo, 1);
        rs_lo += __shfl_xor_sync(0xffffffffu, rs_lo, 2);
        rs_hi += __shfl_xor_sync(0xffffffffu, rs_hi, 1);
        rs_hi += __shfl_xor_sync(0xffffffffu, rs_hi, 2);
        l_lo = l_lo * f_lo + rs_lo;
        l_hi = l_hi * f_hi + rs_hi;

        #pragma unroll
        for (int ni = 0; ni < 8; ni++) {
            acc_o[ni][0] *= f_lo; acc_o[ni][1] *= f_lo;
            acc_o[ni][2] *= f_hi; acc_o[ni][3] *= f_hi;
        }

        __syncwarp();   // P slab visible within warp

        // ---- O += P @ V ----
        const float* Pr = Ps + (w * 16 + grp) * PPITCH;
        #pragma unroll
        for (int kc = 0; kc < 8; kc++) {
            int cc = kc * 8 + tig;
            unsigned pa[4];
            pa[0] = f2tf32(Pr[cc]);
            pa[1] = f2tf32(Pr[8 * PPITCH + cc]);
            pa[2] = f2tf32(Pr[cc + 4]);
            pa[3] = f2tf32(Pr[8 * PPITCH + cc + 4]);
            unsigned bv[8][2];
            #pragma unroll
            for (int ni = 0; ni < 8; ni++) {
                const float* p = Vs_ + (kc * 8 + tig) * VPITCH + ni * 8 + grp;
                bv[ni][0] = f2tf32(p[0]);
                bv[ni][1] = f2tf32(p[4 * VPITCH]);
            }
            #pragma unroll
            for (int ni = 0; ni < 8; ni++)
                mma_tf32(acc_o[ni], pa, bv[ni]);
        }
        __syncwarp();
    }

    // ---- epilogue ----
    float il_lo = 1.0f / l_lo;
    float il_hi = 1.0f / l_hi;
    #pragma unroll
    for (int ni = 0; ni < 8; ni++) {
        int col = ni * 8 + 2 * tig;
        *(float2*)&Og[headoff + (size_t)q_lo * DD + col] =
            make_float2(acc_o[ni][0] * il_lo, acc_o[ni][1] * il_lo);
        *(float2*)&Og[headoff + (size_t)q_hi * DD + col] =
            make_float2(acc_o[ni][2] * il_hi, acc_o[ni][3] * il_hi);
    }
}

// ---------------------------------------------------------------------------
extern "C" void kernel_launch(void* const* d_in, const int* in_sizes, int n_in,
                              void* d_out, int out_size)
{
    const float* x    = (const float*)d_in[0];
    const float* cosb = (const float*)d_in[1];
    const float* sinb = (const float*)d_in[2];
    const float* w_q  = (const float*)d_in[3];
    const float* w_k  = (const float*)d_in[4];
    const float* w_v  = (const float*)d_in[5];
    const float* w_o  = (const float*)d_in[6];
    float* out = (float*)d_out;

    float *q, *k, *v, *attn;
    cudaGetSymbolAddress((void**)&q,    g_q);
    cudaGetSymbolAddress((void**)&k,    g_k);
    cudaGetSymbolAddress((void**)&v,    g_v);
    cudaGetSymbolAddress((void**)&attn, g_attn);

    const int gm_smem = 4 * GTILE * sizeof(float);
    cudaFuncSetAttribute(gemm_tf32_kernel,
                         cudaFuncAttributeMaxDynamicSharedMemorySize, gm_smem);

    const int fa_smem = (2 * KS_BUF + 2 * VS_BUF + 128 * PPITCH) * sizeof(float);
    cudaFuncSetAttribute(flash_attn_tc_kernel,
                         cudaFuncAttributeMaxDynamicSharedMemorySize, fa_smem);

    dim3 ggrid(DD / 128, MTOT / 128);
    gemm_tf32_kernel<<<ggrid, 256, gm_smem>>>(x, w_q, q, MTOT, DD, DD);
    gemm_tf32_kernel<<<ggrid, 256, gm_smem>>>(x, w_k, k, MTOT, DD, DD);
    gemm_tf32_kernel<<<ggrid, 256, gm_smem>>>(x, w_v, v, MTOT, DD, DD);

    int rope_threads = BB * TT * HH * 32;
    rope_kernel<<<rope_threads / 256, 256>>>(q, k, cosb, sinb);

    flash_attn_tc_kernel<<<dim3(TT / 128, BB * HH), 256, fa_smem>>>(q, k, v, attn);

    gemm_tf32_kernel<<<ggrid, 256, gm_smem>>>(attn, w_o, out, MTOT, DD, DD);
}

// round 5
// speedup vs baseline: 4.3911x; 1.2898x over previous
#include <cuda_runtime.h>
#include <cuda_bf16.h>
#include <math.h>

#define BB 4
#define TT 2048
#define DD 1024
#define HH 16
#define HD 64
#define MTOT (BB*TT)          // 8192

// GEMM tiling
#define GPITCH 36
#define GTILE (128*GPITCH)

// flash tiling
#define KPITCH 68
#define VPITCH 72
#define PPITCH 68
#define KS_BUF (64*KPITCH)
#define VS_BUF (64*VPITCH)

__device__ float g_q[MTOT * DD];
__device__ float g_k[MTOT * DD];
__device__ float g_v[MTOT * DD];
__device__ float g_attn[MTOT * DD];
__device__ float g_xr[MTOT * DD];     // tf32-rounded x
__device__ float g_wr[4 * DD * DD];   // tf32-rounded w_q,w_k,w_v,w_o

// ---------------------------------------------------------------------------
__device__ __forceinline__ unsigned smem_u32(const void* p) {
    unsigned r;
    asm("{ .reg .u64 t; cvta.to.shared.u64 t, %1; cvt.u32.u64 %0, t; }"
        : "=r"(r) : "l"(p));
    return r;
}
__device__ __forceinline__ void cp_async16(unsigned s, const void* g) {
    asm volatile("cp.async.cg.shared.global [%0], [%1], 16;" :: "r"(s), "l"(g));
}
__device__ __forceinline__ void cp_commit() { asm volatile("cp.async.commit_group;"); }
__device__ __forceinline__ void cp_wait0()  { asm volatile("cp.async.wait_group 0;"); }
__device__ __forceinline__ unsigned f2tf32(float f) {
    unsigned u;
    asm("cvt.rna.tf32.f32 %0, %1;" : "=r"(u) : "f"(f));
    return u;
}
__device__ __forceinline__ float roundtf(float f) { return __uint_as_float(f2tf32(f)); }
__device__ __forceinline__ void mma_tf32(float* c, const unsigned* a, const unsigned* b) {
    asm volatile(
        "mma.sync.aligned.m16n8k8.row.col.f32.tf32.tf32.f32 "
        "{%0,%1,%2,%3}, {%4,%5,%6,%7}, {%8,%9}, {%0,%1,%2,%3};"
        : "+f"(c[0]), "+f"(c[1]), "+f"(c[2]), "+f"(c[3])
        : "r"(a[0]), "r"(a[1]), "r"(a[2]), "r"(a[3]), "r"(b[0]), "r"(b[1]));
}

// ---------------------------------------------------------------------------
// prep: round arrays to the tf32 grid (rna), float4-vectorized
// ---------------------------------------------------------------------------
__global__ __launch_bounds__(256) void round_x_kernel(const float* __restrict__ in,
                                                      float* __restrict__ out)
{
    int i = blockIdx.x * blockDim.x + threadIdx.x;          // one float4 each
    float4 v = ((const float4*)in)[i];
    v.x = roundtf(v.x); v.y = roundtf(v.y); v.z = roundtf(v.z); v.w = roundtf(v.w);
    ((float4*)out)[i] = v;
}
__global__ __launch_bounds__(256) void round_w_kernel(
    const float* __restrict__ w0, const float* __restrict__ w1,
    const float* __restrict__ w2, const float* __restrict__ w3,
    float* __restrict__ out)
{
    int i = blockIdx.x * blockDim.x + threadIdx.x;          // one float4 each
    const int per = DD * DD / 4;
    int which = i / per;
    int off   = i - which * per;
    const float* src = (which == 0) ? w0 : (which == 1) ? w1 : (which == 2) ? w2 : w3;
    float4 v = ((const float4*)src)[off];
    v.x = roundtf(v.x); v.y = roundtf(v.y); v.z = roundtf(v.z); v.w = roundtf(v.w);
    ((float4*)out)[i] = v;
}

// ---------------------------------------------------------------------------
// TF32 GEMM body:  C[M,N] = A[M,K] @ B[N,K]^T ; operands pre-rounded to tf32.
// CTA tile 128x128, k-step 32, 8 warps (2x4), warp tile 64x32.
// ---------------------------------------------------------------------------
template<bool ROUND_OUT>
__device__ __forceinline__ void gemm_body(
    const float* __restrict__ A, const float* __restrict__ Bw,
    float* __restrict__ C, int M, int N, int K, float* sm)
{
    float* sA = sm;
    float* sB = sm + 2 * GTILE;

    const int tid  = threadIdx.x;
    const int lane = tid & 31;
    const int wid  = tid >> 5;
    const int wm   = wid & 1;
    const int wn   = wid >> 1;
    const int bm   = blockIdx.y * 128;
    const int bn   = blockIdx.x * 128;
    const int grp  = lane >> 2;
    const int tig  = lane & 3;

    const unsigned uA = smem_u32(sA);
    const unsigned uB = smem_u32(sB);

    float acc[4][4][4] = {};
    const int NK = K / 32;

    {
        #pragma unroll
        for (int i = 0; i < 4; i++) {
            int idx = tid + 256 * i;
            int row = idx >> 3;
            int c4  = idx & 7;
            cp_async16(uA + (row * GPITCH + c4 * 4) * 4,
                       A + (size_t)(bm + row) * K + c4 * 4);
            cp_async16(uB + (row * GPITCH + c4 * 4) * 4,
                       Bw + (size_t)(bn + row) * K + c4 * 4);
        }
        cp_commit();
    }

    for (int kt = 0; kt < NK; kt++) {
        cp_wait0();
        __syncthreads();

        int nxt = kt + 1;
        if (nxt < NK) {
            int nb = nxt & 1;
            #pragma unroll
            for (int i = 0; i < 4; i++) {
                int idx = tid + 256 * i;
                int row = idx >> 3;
                int c4  = idx & 7;
                cp_async16(uA + (nb * GTILE + row * GPITCH + c4 * 4) * 4,
                           A + (size_t)(bm + row) * K + nxt * 32 + c4 * 4);
                cp_async16(uB + (nb * GTILE + row * GPITCH + c4 * 4) * 4,
                           Bw + (size_t)(bn + row) * K + nxt * 32 + c4 * 4);
            }
            cp_commit();
        }

        const unsigned* As_ = (const unsigned*)(sA + (kt & 1) * GTILE);
        const unsigned* Bs_ = (const unsigned*)(sB + (kt & 1) * GTILE);

        #pragma unroll
        for (int ks = 0; ks < 4; ks++) {
            int kc = ks * 8 + tig;
            unsigned a[4][4], b[4][2];
            #pragma unroll
            for (int mi = 0; mi < 4; mi++) {
                const unsigned* p = As_ + (wm * 64 + mi * 16 + grp) * GPITCH + kc;
                a[mi][0] = p[0];
                a[mi][1] = p[8 * GPITCH];
                a[mi][2] = p[4];
                a[mi][3] = p[8 * GPITCH + 4];
            }
            #pragma unroll
            for (int ni = 0; ni < 4; ni++) {
                const unsigned* p = Bs_ + (wn * 32 + ni * 8 + grp) * GPITCH + kc;
                b[ni][0] = p[0];
                b[ni][1] = p[4];
            }
            #pragma unroll
            for (int mi = 0; mi < 4; mi++)
                #pragma unroll
                for (int ni = 0; ni < 4; ni++)
                    mma_tf32(acc[mi][ni], a[mi], b[ni]);
        }
    }

    #pragma unroll
    for (int mi = 0; mi < 4; mi++) {
        int r0 = bm + wm * 64 + mi * 16 + grp;
        #pragma unroll
        for (int ni = 0; ni < 4; ni++) {
            int col = bn + wn * 32 + ni * 8 + tig * 2;
            float2 lo, hi;
            if (ROUND_OUT) {
                lo = make_float2(roundtf(acc[mi][ni][0]), roundtf(acc[mi][ni][1]));
                hi = make_float2(roundtf(acc[mi][ni][2]), roundtf(acc[mi][ni][3]));
            } else {
                lo = make_float2(acc[mi][ni][0], acc[mi][ni][1]);
                hi = make_float2(acc[mi][ni][2], acc[mi][ni][3]);
            }
            *(float2*)&C[(size_t)r0 * N + col]       = lo;
            *(float2*)&C[(size_t)(r0 + 8) * N + col] = hi;
        }
    }
}

// fused QKV: grid.z selects weight slice + destination; outputs tf32-rounded
__global__ __launch_bounds__(256) void gemm_qkv_kernel(
    const float* __restrict__ A, const float* __restrict__ W,
    float* __restrict__ Cq, float* __restrict__ Ck, float* __restrict__ Cv)
{
    extern __shared__ float sm[];
    int z = blockIdx.z;
    float* C = (z == 0) ? Cq : (z == 1) ? Ck : Cv;
    gemm_body<true>(A, W + (size_t)z * DD * DD, C, MTOT, DD, DD, sm);
}
// output projection: no rounding of C
__global__ __launch_bounds__(256) void gemm_out_kernel(
    const float* __restrict__ A, const float* __restrict__ W, float* __restrict__ C)
{
    extern __shared__ float sm[];
    gemm_body<false>(A, W, C, MTOT, DD, DD, sm);
}

// ---------------------------------------------------------------------------
// RoPE (in-place on Q and K); outputs tf32-rounded
// ---------------------------------------------------------------------------
__global__ __launch_bounds__(256) void rope_kernel(
    float* __restrict__ q, float* __restrict__ k,
    const float* __restrict__ cosb, const float* __restrict__ sinb)
{
    int idx = blockIdx.x * blockDim.x + threadIdx.x;
    if (idx >= BB * TT * HH * 32) return;
    int d  = idx & 31;
    int h  = (idx >> 5) & (HH - 1);
    int t  = (idx >> 9) & (TT - 1);
    int b  = idx >> 20;

    size_t base = ((size_t)(b * TT + t)) * DD + h * HD;
    float c1 = cosb[t * HD + d],      s1 = sinb[t * HD + d];
    float c2 = cosb[t * HD + d + 32], s2 = sinb[t * HD + d + 32];

    float q1 = q[base + d], q2 = q[base + d + 32];
    q[base + d]      = roundtf(q1 * c1 - q2 * s1);
    q[base + d + 32] = roundtf(q2 * c2 + q1 * s2);

    float k1 = k[base + d], k2 = k[base + d + 32];
    k[base + d]      = roundtf(k1 * c1 - k2 * s1);
    k[base + d + 32] = roundtf(k2 * c2 + k1 * s2);
}

// ---------------------------------------------------------------------------
// Tensor-core causal flash attention (tf32 mma); Q/K/V pre-rounded in gmem.
// CTA: 128 q-rows of one (b,h); 8 warps. K/V tiles of 64 keys, double-buffered.
// ---------------------------------------------------------------------------
__global__ __launch_bounds__(256) void flash_attn_tc_kernel(
    const float* __restrict__ Qg, const float* __restrict__ Kg,
    const float* __restrict__ Vg, float* __restrict__ Og)
{
    extern __shared__ float sm[];
    float* Ks = sm;
    float* Vs = Ks + 2 * KS_BUF;
    float* Ps = Vs + 2 * VS_BUF;

    const int tid  = threadIdx.x;
    const int lane = tid & 31;
    const int w    = tid >> 5;
    const int grp  = lane >> 2;
    const int tig  = lane & 3;
    const int qb   = blockIdx.x;
    const int bh   = blockIdx.y;
    const int b    = bh >> 4;
    const int h    = bh & 15;

    const size_t headoff = (size_t)(b * TT) * DD + (size_t)h * HD;
    const float scale = 0.125f;
    const unsigned uK = smem_u32(Ks);
    const unsigned uV = smem_u32(Vs);

    // stage Q tile [128 x 64] into Ps, then lift to register frags (raw bits)
    #pragma unroll
    for (int i = 0; i < 8; i++) {
        int idx = i * 256 + tid;
        int row = idx >> 4;
        int c4  = idx & 15;
        float4 v4 = *(const float4*)&Qg[headoff + (size_t)(qb*128 + row) * DD + c4*4];
        *(float4*)&Ps[row * PPITCH + c4*4] = v4;
    }
    __syncthreads();

    unsigned qa[8][4];
    {
        const unsigned* p0 = (const unsigned*)(Ps + (w * 16 + grp) * PPITCH);
        #pragma unroll
        for (int ks = 0; ks < 8; ks++) {
            int kc = ks * 8 + tig;
            qa[ks][0] = p0[kc];
            qa[ks][1] = p0[8 * PPITCH + kc];
            qa[ks][2] = p0[kc + 4];
            qa[ks][3] = p0[8 * PPITCH + kc + 4];
        }
    }
    __syncwarp();

    float acc_o[8][4] = {};
    float m_lo = -1e30f, m_hi = -1e30f;
    float l_lo = 0.0f,   l_hi = 0.0f;

    const int kb_max = 2 * qb + 1;
    const int q_lo = qb * 128 + w * 16 + grp;
    const int q_hi = q_lo + 8;

    {
        #pragma unroll
        for (int i = 0; i < 8; i++) {
            int idx = i * 256 + tid;
            int row = (idx >> 4) & 63;
            int c4  = idx & 15;
            size_t goff = headoff + (size_t)row * DD + c4 * 4;
            if (idx < 1024)
                cp_async16(uK + (row * KPITCH + c4 * 4) * 4, Kg + goff);
            else
                cp_async16(uV + (row * VPITCH + c4 * 4) * 4, Vg + goff);
        }
        cp_commit();
    }

    for (int kb = 0; kb <= kb_max; kb++) {
        cp_wait0();
        __syncthreads();

        if (kb < kb_max) {
            int nb = (kb + 1) & 1;
            #pragma unroll
            for (int i = 0; i < 8; i++) {
                int idx = i * 256 + tid;
                int row = (idx >> 4) & 63;
                int c4  = idx & 15;
                size_t goff = headoff + (size_t)((kb+1)*64 + row) * DD + c4 * 4;
                if (idx < 1024)
                    cp_async16(uK + (nb * KS_BUF + row * KPITCH + c4 * 4) * 4, Kg + goff);
                else
                    cp_async16(uV + (nb * VS_BUF + row * VPITCH + c4 * 4) * 4, Vg + goff);
            }
            cp_commit();
        }

        const unsigned* Ks_ = (const unsigned*)(Ks + (kb & 1) * KS_BUF);
        const unsigned* Vs_ = (const unsigned*)(Vs + (kb & 1) * VS_BUF);

        // S = Q @ K^T
        float acc_s[8][4] = {};
        #pragma unroll
        for (int ks = 0; ks < 8; ks++) {
            int kc = ks * 8 + tig;
            unsigned bfr[8][2];
            #pragma unroll
            for (int ni = 0; ni < 8; ni++) {
                const unsigned* p = Ks_ + (ni * 8 + grp) * KPITCH + kc;
                bfr[ni][0] = p[0];
                bfr[ni][1] = p[4];
            }
            #pragma unroll
            for (int ni = 0; ni < 8; ni++)
                mma_tf32(acc_s[ni], qa[ks], bfr[ni]);
        }

        // scale + causal mask
        const bool diag = (kb >= 2 * qb);
        #pragma unroll
        for (int ni = 0; ni < 8; ni++) {
            int k0 = kb * 64 + ni * 8 + 2 * tig;
            if (diag) {
                acc_s[ni][0] = (k0     <= q_lo) ? acc_s[ni][0] * scale : -1e30f;
                acc_s[ni][1] = (k0 + 1 <= q_lo) ? acc_s[ni][1] * scale : -1e30f;
                acc_s[ni][2] = (k0     <= q_hi) ? acc_s[ni][2] * scale : -1e30f;
                acc_s[ni][3] = (k0 + 1 <= q_hi) ? acc_s[ni][3] * scale : -1e30f;
            } else {
                acc_s[ni][0] *= scale; acc_s[ni][1] *= scale;
                acc_s[ni][2] *= scale; acc_s[ni][3] *= scale;
            }
        }

        // online softmax
        float tm_lo = -1e30f, tm_hi = -1e30f;
        #pragma unroll
        for (int ni = 0; ni < 8; ni++) {
            tm_lo = fmaxf(tm_lo, fmaxf(acc_s[ni][0], acc_s[ni][1]));
            tm_hi = fmaxf(tm_hi, fmaxf(acc_s[ni][2], acc_s[ni][3]));
        }
        tm_lo = fmaxf(tm_lo, __shfl_xor_sync(0xffffffffu, tm_lo, 1));
        tm_lo = fmaxf(tm_lo, __shfl_xor_sync(0xffffffffu, tm_lo, 2));
        tm_hi = fmaxf(tm_hi, __shfl_xor_sync(0xffffffffu, tm_hi, 1));
        tm_hi = fmaxf(tm_hi, __shfl_xor_sync(0xffffffffu, tm_hi, 2));

        float mn_lo = fmaxf(m_lo, tm_lo);
        float mn_hi = fmaxf(m_hi, tm_hi);
        float f_lo = __expf(m_lo - mn_lo);
        float f_hi = __expf(m_hi - mn_hi);
        m_lo = mn_lo; m_hi = mn_hi;

        float rs_lo = 0.0f, rs_hi = 0.0f;
        float* Pw = Ps + (w * 16 + grp) * PPITCH;
        #pragma unroll
        for (int ni = 0; ni < 8; ni++) {
            float p0 = __expf(acc_s[ni][0] - mn_lo);
            float p1 = __expf(acc_s[ni][1] - mn_lo);
            float p2 = __expf(acc_s[ni][2] - mn_hi);
            float p3 = __expf(acc_s[ni][3] - mn_hi);
            rs_lo += p0 + p1;
            rs_hi += p2 + p3;
            *(float2*)&Pw[ni * 8 + 2 * tig]              = make_float2(p0, p1);
            *(float2*)&Pw[8 * PPITCH + ni * 8 + 2 * tig] = make_float2(p2, p3);
        }
        rs_lo += __shfl_xor_sync(0xffffffffu, rs_lo, 1);
        rs_lo += __shfl_xor_sync(0xffffffffu, rs_lo, 2);
        rs_hi += __shfl_xor_sync(0xffffffffu, rs_hi, 1);
        rs_hi += __shfl_xor_sync(0xffffffffu, rs_hi, 2);
        l_lo = l_lo * f_lo + rs_lo;
        l_hi = l_hi * f_hi + rs_hi;

        #pragma unroll
        for (int ni = 0; ni < 8; ni++) {
            acc_o[ni][0] *= f_lo; acc_o[ni][1] *= f_lo;
            acc_o[ni][2] *= f_hi; acc_o[ni][3] *= f_hi;
        }

        __syncwarp();

        // O += P @ V  (P needs cvt; V pre-rounded)
        const float* Pr = Ps + (w * 16 + grp) * PPITCH;
        #pragma unroll
        for (int kc = 0; kc < 8; kc++) {
            int cc = kc * 8 + tig;
            unsigned pa[4];
            pa[0] = f2tf32(Pr[cc]);
            pa[1] = f2tf32(Pr[8 * PPITCH + cc]);
            pa[2] = f2tf32(Pr[cc + 4]);
            pa[3] = f2tf32(Pr[8 * PPITCH + cc + 4]);
            unsigned bv[8][2];
            #pragma unroll
            for (int ni = 0; ni < 8; ni++) {
                const unsigned* p = Vs_ + (kc * 8 + tig) * VPITCH + ni * 8 + grp;
                bv[ni][0] = p[0];
                bv[ni][1] = p[4 * VPITCH];
            }
            #pragma unroll
            for (int ni = 0; ni < 8; ni++)
                mma_tf32(acc_o[ni], pa, bv[ni]);
        }
        __syncwarp();
    }

    // epilogue: normalize + round (feeds the w_o GEMM)
    float il_lo = 1.0f / l_lo;
    float il_hi = 1.0f / l_hi;
    #pragma unroll
    for (int ni = 0; ni < 8; ni++) {
        int col = ni * 8 + 2 * tig;
        *(float2*)&Og[headoff + (size_t)q_lo * DD + col] =
            make_float2(roundtf(acc_o[ni][0] * il_lo), roundtf(acc_o[ni][1] * il_lo));
        *(float2*)&Og[headoff + (size_t)q_hi * DD + col] =
            make_float2(roundtf(acc_o[ni][2] * il_hi), roundtf(acc_o[ni][3] * il_hi));
    }
}

// ---------------------------------------------------------------------------
extern "C" void kernel_launch(void* const* d_in, const int* in_sizes, int n_in,
                              void* d_out, int out_size)
{
    const float* x    = (const float*)d_in[0];
    const float* cosb = (const float*)d_in[1];
    const float* sinb = (const float*)d_in[2];
    const float* w_q  = (const float*)d_in[3];
    const float* w_k  = (const float*)d_in[4];
    const float* w_v  = (const float*)d_in[5];
    const float* w_o  = (const float*)d_in[6];
    float* out = (float*)d_out;

    float *q, *k, *v, *attn, *xr, *wr;
    cudaGetSymbolAddress((void**)&q,    g_q);
    cudaGetSymbolAddress((void**)&k,    g_k);
    cudaGetSymbolAddress((void**)&v,    g_v);
    cudaGetSymbolAddress((void**)&attn, g_attn);
    cudaGetSymbolAddress((void**)&xr,   g_xr);
    cudaGetSymbolAddress((void**)&wr,   g_wr);

    const int gm_smem = 4 * GTILE * sizeof(float);
    cudaFuncSetAttribute(gemm_qkv_kernel,
                         cudaFuncAttributeMaxDynamicSharedMemorySize, gm_smem);
    cudaFuncSetAttribute(gemm_out_kernel,
                         cudaFuncAttributeMaxDynamicSharedMemorySize, gm_smem);

    const int fa_smem = (2 * KS_BUF + 2 * VS_BUF + 128 * PPITCH) * sizeof(float);
    cudaFuncSetAttribute(flash_attn_tc_kernel,
                         cudaFuncAttributeMaxDynamicSharedMemorySize, fa_smem);

    // prep: round operands to tf32 grid
    round_x_kernel<<<(MTOT * DD / 4) / 256, 256>>>(x, xr);
    round_w_kernel<<<(4 * DD * DD / 4) / 256, 256>>>(w_q, w_k, w_v, w_o, wr);

    // fused QKV projection (outputs rounded)
    dim3 qkvgrid(DD / 128, MTOT / 128, 3);
    gemm_qkv_kernel<<<qkvgrid, 256, gm_smem>>>(xr, wr, q, k, v);

    int rope_threads = BB * TT * HH * 32;
    rope_kernel<<<rope_threads / 256, 256>>>(q, k, cosb, sinb);

    flash_attn_tc_kernel<<<dim3(TT / 128, BB * HH), 256, fa_smem>>>(q, k, v, attn);

    dim3 ogrid(DD / 128, MTOT / 128);
    gemm_out_kernel<<<ogrid, 256, gm_smem>>>(attn, wr + (size_t)3 * DD * DD, out);
}

// round 6
// speedup vs baseline: 4.4567x; 1.0149x over previous
#include <cuda_runtime.h>
#include <cuda_bf16.h>
#include <math.h>

#define BB 4
#define TT 2048
#define DD 1024
#define HH 16
#define HD 64
#define MTOT (BB*TT)          // 8192

// GEMM tiling: CTA 256x128, warp tile 64x64, 8 warps (4m x 2n)
#define GPITCH 36
#define GA_TILE (256*GPITCH)
#define GB_TILE (128*GPITCH)

// flash tiling
#define KPITCH 68
#define VPITCH 72
#define PPITCH 68
#define KS_BUF (64*KPITCH)
#define VS_BUF (64*VPITCH)

__device__ float g_q[MTOT * DD];
__device__ float g_k[MTOT * DD];
__device__ float g_v[MTOT * DD];
__device__ float g_attn[MTOT * DD];
__device__ float g_xr[MTOT * DD];     // tf32-rounded x
__device__ float g_wr[4 * DD * DD];   // tf32-rounded w_q,w_k,w_v,w_o

// ---------------------------------------------------------------------------
__device__ __forceinline__ unsigned smem_u32(const void* p) {
    unsigned r;
    asm("{ .reg .u64 t; cvta.to.shared.u64 t, %1; cvt.u32.u64 %0, t; }"
        : "=r"(r) : "l"(p));
    return r;
}
__device__ __forceinline__ void cp_async16(unsigned s, const void* g) {
    asm volatile("cp.async.cg.shared.global [%0], [%1], 16;" :: "r"(s), "l"(g));
}
__device__ __forceinline__ void cp_commit() { asm volatile("cp.async.commit_group;"); }
__device__ __forceinline__ void cp_wait0()  { asm volatile("cp.async.wait_group 0;"); }
__device__ __forceinline__ unsigned f2tf32(float f) {
    unsigned u;
    asm("cvt.rna.tf32.f32 %0, %1;" : "=r"(u) : "f"(f));
    return u;
}
__device__ __forceinline__ float roundtf(float f) { return __uint_as_float(f2tf32(f)); }
__device__ __forceinline__ void mma_tf32(float* c, const unsigned* a, const unsigned* b) {
    asm volatile(
        "mma.sync.aligned.m16n8k8.row.col.f32.tf32.tf32.f32 "
        "{%0,%1,%2,%3}, {%4,%5,%6,%7}, {%8,%9}, {%0,%1,%2,%3};"
        : "+f"(c[0]), "+f"(c[1]), "+f"(c[2]), "+f"(c[3])
        : "r"(a[0]), "r"(a[1]), "r"(a[2]), "r"(a[3]), "r"(b[0]), "r"(b[1]));
}

// ---------------------------------------------------------------------------
// prep: round arrays to tf32 grid
// ---------------------------------------------------------------------------
__global__ __launch_bounds__(256) void round_x_kernel(const float* __restrict__ in,
                                                      float* __restrict__ out)
{
    int i = blockIdx.x * blockDim.x + threadIdx.x;
    float4 v = ((const float4*)in)[i];
    v.x = roundtf(v.x); v.y = roundtf(v.y); v.z = roundtf(v.z); v.w = roundtf(v.w);
    ((float4*)out)[i] = v;
}
__global__ __launch_bounds__(256) void round_w_kernel(
    const float* __restrict__ w0, const float* __restrict__ w1,
    const float* __restrict__ w2, const float* __restrict__ w3,
    float* __restrict__ out)
{
    int i = blockIdx.x * blockDim.x + threadIdx.x;
    const int per = DD * DD / 4;
    int which = i / per;
    int off   = i - which * per;
    const float* src = (which == 0) ? w0 : (which == 1) ? w1 : (which == 2) ? w2 : w3;
    float4 v = ((const float4*)src)[off];
    v.x = roundtf(v.x); v.y = roundtf(v.y); v.z = roundtf(v.z); v.w = roundtf(v.w);
    ((float4*)out)[i] = v;
}

// ---------------------------------------------------------------------------
// TF32 GEMM body: C[M,N] = A[M,K] @ B[N,K]^T ; operands pre-rounded.
// CTA tile 256x128, warp tile 64x64 (LDS/MMA = 1.0), k-step 32, double-buffered.
// ---------------------------------------------------------------------------
template<bool ROUND_OUT>
__device__ __forceinline__ void gemm_body(
    const float* __restrict__ A, const float* __restrict__ Bw,
    float* __restrict__ C, int M, int N, int K, float* sm)
{
    float* sA = sm;                      // [2][256][GPITCH]
    float* sB = sm + 2 * GA_TILE;        // [2][128][GPITCH]

    const int tid  = threadIdx.x;
    const int lane = tid & 31;
    const int wid  = tid >> 5;
    const int wm   = wid & 3;            // 4 m-warps
    const int wn   = wid >> 2;           // 2 n-warps
    const int bm   = blockIdx.y * 256;
    const int bn   = blockIdx.x * 128;
    const int grp  = lane >> 2;
    const int tig  = lane & 3;

    const unsigned uA = smem_u32(sA);
    const unsigned uB = smem_u32(sB);

    float acc[4][8][4] = {};
    const int NK = K / 32;

    {
        #pragma unroll
        for (int i = 0; i < 8; i++) {    // A: 256 rows x 8 float4
            int idx = tid + 256 * i;
            int row = idx >> 3;
            int c4  = idx & 7;
            cp_async16(uA + (row * GPITCH + c4 * 4) * 4,
                       A + (size_t)(bm + row) * K + c4 * 4);
        }
        #pragma unroll
        for (int i = 0; i < 4; i++) {    // B: 128 rows x 8 float4
            int idx = tid + 256 * i;
            int row = idx >> 3;
            int c4  = idx & 7;
            cp_async16(uB + (row * GPITCH + c4 * 4) * 4,
                       Bw + (size_t)(bn + row) * K + c4 * 4);
        }
        cp_commit();
    }

    for (int kt = 0; kt < NK; kt++) {
        cp_wait0();
        __syncthreads();

        int nxt = kt + 1;
        if (nxt < NK) {
            int nb = nxt & 1;
            #pragma unroll
            for (int i = 0; i < 8; i++) {
                int idx = tid + 256 * i;
                int row = idx >> 3;
                int c4  = idx & 7;
                cp_async16(uA + (nb * GA_TILE + row * GPITCH + c4 * 4) * 4,
                           A + (size_t)(bm + row) * K + nxt * 32 + c4 * 4);
            }
            #pragma unroll
            for (int i = 0; i < 4; i++) {
                int idx = tid + 256 * i;
                int row = idx >> 3;
                int c4  = idx & 7;
                cp_async16(uB + (nb * GB_TILE + row * GPITCH + c4 * 4) * 4,
                           Bw + (size_t)(bn + row) * K + nxt * 32 + c4 * 4);
            }
            cp_commit();
        }

        const unsigned* As_ = (const unsigned*)(sA + (kt & 1) * GA_TILE);
        const unsigned* Bs_ = (const unsigned*)(sB + (kt & 1) * GB_TILE);

        #pragma unroll
        for (int ks = 0; ks < 4; ks++) {
            int kc = ks * 8 + tig;
            unsigned a[4][4], b[8][2];
            #pragma unroll
            for (int mi = 0; mi < 4; mi++) {
                const unsigned* p = As_ + (wm * 64 + mi * 16 + grp) * GPITCH + kc;
                a[mi][0] = p[0];
                a[mi][1] = p[8 * GPITCH];
                a[mi][2] = p[4];
                a[mi][3] = p[8 * GPITCH + 4];
            }
            #pragma unroll
            for (int ni = 0; ni < 8; ni++) {
                const unsigned* p = Bs_ + (wn * 64 + ni * 8 + grp) * GPITCH + kc;
                b[ni][0] = p[0];
                b[ni][1] = p[4];
            }
            #pragma unroll
            for (int mi = 0; mi < 4; mi++)
                #pragma unroll
                for (int ni = 0; ni < 8; ni++)
                    mma_tf32(acc[mi][ni], a[mi], b[ni]);
        }
    }

    #pragma unroll
    for (int mi = 0; mi < 4; mi++) {
        int r0 = bm + wm * 64 + mi * 16 + grp;
        #pragma unroll
        for (int ni = 0; ni < 8; ni++) {
            int col = bn + wn * 64 + ni * 8 + tig * 2;
            float2 lo, hi;
            if (ROUND_OUT) {
                lo = make_float2(roundtf(acc[mi][ni][0]), roundtf(acc[mi][ni][1]));
                hi = make_float2(roundtf(acc[mi][ni][2]), roundtf(acc[mi][ni][3]));
            } else {
                lo = make_float2(acc[mi][ni][0], acc[mi][ni][1]);
                hi = make_float2(acc[mi][ni][2], acc[mi][ni][3]);
            }
            *(float2*)&C[(size_t)r0 * N + col]       = lo;
            *(float2*)&C[(size_t)(r0 + 8) * N + col] = hi;
        }
    }
}

__global__ __launch_bounds__(256) void gemm_qkv_kernel(
    const float* __restrict__ A, const float* __restrict__ W,
    float* __restrict__ Cq, float* __restrict__ Ck, float* __restrict__ Cv)
{
    extern __shared__ float sm[];
    int z = blockIdx.z;
    float* C = (z == 0) ? Cq : (z == 1) ? Ck : Cv;
    gemm_body<true>(A, W + (size_t)z * DD * DD, C, MTOT, DD, DD, sm);
}
__global__ __launch_bounds__(256) void gemm_out_kernel(
    const float* __restrict__ A, const float* __restrict__ W, float* __restrict__ C)
{
    extern __shared__ float sm[];
    gemm_body<false>(A, W, C, MTOT, DD, DD, sm);
}

// ---------------------------------------------------------------------------
// RoPE (in-place); outputs tf32-rounded
// ---------------------------------------------------------------------------
__global__ __launch_bounds__(256) void rope_kernel(
    float* __restrict__ q, float* __restrict__ k,
    const float* __restrict__ cosb, const float* __restrict__ sinb)
{
    int idx = blockIdx.x * blockDim.x + threadIdx.x;
    if (idx >= BB * TT * HH * 32) return;
    int d  = idx & 31;
    int h  = (idx >> 5) & (HH - 1);
    int t  = (idx >> 9) & (TT - 1);
    int b  = idx >> 20;

    size_t base = ((size_t)(b * TT + t)) * DD + h * HD;
    float c1 = cosb[t * HD + d],      s1 = sinb[t * HD + d];
    float c2 = cosb[t * HD + d + 32], s2 = sinb[t * HD + d + 32];

    float q1 = q[base + d], q2 = q[base + d + 32];
    q[base + d]      = roundtf(q1 * c1 - q2 * s1);
    q[base + d + 32] = roundtf(q2 * c2 + q1 * s2);

    float k1 = k[base + d], k2 = k[base + d + 32];
    k[base + d]      = roundtf(k1 * c1 - k2 * s1);
    k[base + d + 32] = roundtf(k2 * c2 + k1 * s2);
}

// ---------------------------------------------------------------------------
// Tensor-core causal flash attention. BQ=128, 4 warps x 32 q-rows each
// (two 16-row mma tile sets per warp -> K/V fragments reused 2x).
// ---------------------------------------------------------------------------
__global__ __launch_bounds__(128) void flash_attn_tc_kernel(
    const float* __restrict__ Qg, const float* __restrict__ Kg,
    const float* __restrict__ Vg, float* __restrict__ Og)
{
    extern __shared__ float sm[];
    float* Ks = sm;
    float* Vs = Ks + 2 * KS_BUF;
    float* Ps = Vs + 2 * VS_BUF;          // [128][PPITCH]

    const int tid  = threadIdx.x;
    const int lane = tid & 31;
    const int w    = tid >> 5;            // warp 0..3
    const int grp  = lane >> 2;
    const int tig  = lane & 3;
    const int qb   = blockIdx.x;
    const int bh   = blockIdx.y;
    const int b    = bh >> 4;
    const int h    = bh & 15;

    const size_t headoff = (size_t)(b * TT) * DD + (size_t)h * HD;
    const float scale = 0.125f;
    const unsigned uK = smem_u32(Ks);
    const unsigned uV = smem_u32(Vs);

    // stage Q tile [128 x 64] into Ps
    #pragma unroll
    for (int i = 0; i < 16; i++) {
        int idx = i * 128 + tid;          // 0..2047
        int row = idx >> 4;
        int c4  = idx & 15;
        float4 v4 = *(const float4*)&Qg[headoff + (size_t)(qb*128 + row) * DD + c4*4];
        *(float4*)&Ps[row * PPITCH + c4*4] = v4;
    }
    __syncthreads();

    unsigned qa[2][8][4];                 // two 16-row sets
    #pragma unroll
    for (int st = 0; st < 2; st++) {
        const unsigned* p0 = (const unsigned*)(Ps + (w * 32 + st * 16 + grp) * PPITCH);
        #pragma unroll
        for (int ks = 0; ks < 8; ks++) {
            int kc = ks * 8 + tig;
            qa[st][ks][0] = p0[kc];
            qa[st][ks][1] = p0[8 * PPITCH + kc];
            qa[st][ks][2] = p0[kc + 4];
            qa[st][ks][3] = p0[8 * PPITCH + kc + 4];
        }
    }
    __syncwarp();

    float acc_o[2][8][4] = {};
    float mrow[4] = {-1e30f, -1e30f, -1e30f, -1e30f};  // lo0,hi0,lo1,hi1
    float lrow[4] = {};

    const int kb_max = 2 * qb + 1;
    const int qrow0 = qb * 128 + w * 32 + grp;   // set0 c0/c1 row
    // set0 hi = +8; set1 lo = +16; set1 hi = +24

    {
        #pragma unroll
        for (int i = 0; i < 16; i++) {
            int idx = i * 128 + tid;
            int row = (idx >> 4) & 63;
            int c4  = idx & 15;
            size_t goff = headoff + (size_t)row * DD + c4 * 4;
            if (idx < 1024)
                cp_async16(uK + (row * KPITCH + c4 * 4) * 4, Kg + goff);
            else
                cp_async16(uV + (row * VPITCH + c4 * 4) * 4, Vg + goff);
        }
        cp_commit();
    }

    for (int kb = 0; kb <= kb_max; kb++) {
        cp_wait0();
        __syncthreads();

        if (kb < kb_max) {
            int nb = (kb + 1) & 1;
            #pragma unroll
            for (int i = 0; i < 16; i++) {
                int idx = i * 128 + tid;
                int row = (idx >> 4) & 63;
                int c4  = idx & 15;
                size_t goff = headoff + (size_t)((kb+1)*64 + row) * DD + c4 * 4;
                if (idx < 1024)
                    cp_async16(uK + (nb * KS_BUF + row * KPITCH + c4 * 4) * 4, Kg + goff);
                else
                    cp_async16(uV + (nb * VS_BUF + row * VPITCH + c4 * 4) * 4, Vg + goff);
            }
            cp_commit();
        }

        const unsigned* Ks_ = (const unsigned*)(Ks + (kb & 1) * KS_BUF);
        const unsigned* Vs_ = (const unsigned*)(Vs + (kb & 1) * VS_BUF);

        // ---- S = Q @ K^T for both row sets (K frags loaded once) ----
        float acc_s[2][8][4] = {};
        #pragma unroll
        for (int ks = 0; ks < 8; ks++) {
            int kc = ks * 8 + tig;
            unsigned bfr[8][2];
            #pragma unroll
            for (int ni = 0; ni < 8; ni++) {
                const unsigned* p = Ks_ + (ni * 8 + grp) * KPITCH + kc;
                bfr[ni][0] = p[0];
                bfr[ni][1] = p[4];
            }
            #pragma unroll
            for (int ni = 0; ni < 8; ni++) {
                mma_tf32(acc_s[0][ni], qa[0][ks], bfr[ni]);
                mma_tf32(acc_s[1][ni], qa[1][ks], bfr[ni]);
            }
        }

        // ---- scale + causal mask ----
        const bool diag = (kb >= 2 * qb);
        #pragma unroll
        for (int st = 0; st < 2; st++) {
            int qlo = qrow0 + st * 16;
            int qhi = qlo + 8;
            #pragma unroll
            for (int ni = 0; ni < 8; ni++) {
                int k0 = kb * 64 + ni * 8 + 2 * tig;
                if (diag) {
                    acc_s[st][ni][0] = (k0     <= qlo) ? acc_s[st][ni][0] * scale : -1e30f;
                    acc_s[st][ni][1] = (k0 + 1 <= qlo) ? acc_s[st][ni][1] * scale : -1e30f;
                    acc_s[st][ni][2] = (k0     <= qhi) ? acc_s[st][ni][2] * scale : -1e30f;
                    acc_s[st][ni][3] = (k0 + 1 <= qhi) ? acc_s[st][ni][3] * scale : -1e30f;
                } else {
                    acc_s[st][ni][0] *= scale; acc_s[st][ni][1] *= scale;
                    acc_s[st][ni][2] *= scale; acc_s[st][ni][3] *= scale;
                }
            }
        }

        // ---- online softmax (4 row-groups: st*2 + {lo,hi}) ----
        #pragma unroll
        for (int st = 0; st < 2; st++) {
            float tm_lo = -1e30f, tm_hi = -1e30f;
            #pragma unroll
            for (int ni = 0; ni < 8; ni++) {
                tm_lo = fmaxf(tm_lo, fmaxf(acc_s[st][ni][0], acc_s[st][ni][1]));
                tm_hi = fmaxf(tm_hi, fmaxf(acc_s[st][ni][2], acc_s[st][ni][3]));
            }
            tm_lo = fmaxf(tm_lo, __shfl_xor_sync(0xffffffffu, tm_lo, 1));
            tm_lo = fmaxf(tm_lo, __shfl_xor_sync(0xffffffffu, tm_lo, 2));
            tm_hi = fmaxf(tm_hi, __shfl_xor_sync(0xffffffffu, tm_hi, 1));
            tm_hi = fmaxf(tm_hi, __shfl_xor_sync(0xffffffffu, tm_hi, 2));

            float mn_lo = fmaxf(mrow[st*2+0], tm_lo);
            float mn_hi = fmaxf(mrow[st*2+1], tm_hi);
            float f_lo = __expf(mrow[st*2+0] - mn_lo);
            float f_hi = __expf(mrow[st*2+1] - mn_hi);
            mrow[st*2+0] = mn_lo; mrow[st*2+1] = mn_hi;

            float rs_lo = 0.0f, rs_hi = 0.0f;
            float* Pw = Ps + (w * 32 + st * 16 + grp) * PPITCH;
            #pragma unroll
            for (int ni = 0; ni < 8; ni++) {
                float p0 = __expf(acc_s[st][ni][0] - mn_lo);
                float p1 = __expf(acc_s[st][ni][1] - mn_lo);
                float p2 = __expf(acc_s[st][ni][2] - mn_hi);
                float p3 = __expf(acc_s[st][ni][3] - mn_hi);
                rs_lo += p0 + p1;
                rs_hi += p2 + p3;
                *(float2*)&Pw[ni * 8 + 2 * tig]              = make_float2(p0, p1);
                *(float2*)&Pw[8 * PPITCH + ni * 8 + 2 * tig] = make_float2(p2, p3);
            }
            rs_lo += __shfl_xor_sync(0xffffffffu, rs_lo, 1);
            rs_lo += __shfl_xor_sync(0xffffffffu, rs_lo, 2);
            rs_hi += __shfl_xor_sync(0xffffffffu, rs_hi, 1);
            rs_hi += __shfl_xor_sync(0xffffffffu, rs_hi, 2);
            lrow[st*2+0] = lrow[st*2+0] * f_lo + rs_lo;
            lrow[st*2+1] = lrow[st*2+1] * f_hi + rs_hi;

            #pragma unroll
            for (int ni = 0; ni < 8; ni++) {
                acc_o[st][ni][0] *= f_lo; acc_o[st][ni][1] *= f_lo;
                acc_o[st][ni][2] *= f_hi; acc_o[st][ni][3] *= f_hi;
            }
        }

        __syncwarp();

        // ---- O += P @ V (V frags loaded once, used by both sets) ----
        const float* Pr0 = Ps + (w * 32 + grp) * PPITCH;
        const float* Pr1 = Ps + (w * 32 + 16 + grp) * PPITCH;
        #pragma unroll
        for (int kc = 0; kc < 8; kc++) {
            int cc = kc * 8 + tig;
            unsigned pa0[4], pa1[4];
            pa0[0] = f2tf32(Pr0[cc]);
            pa0[1] = f2tf32(Pr0[8 * PPITCH + cc]);
            pa0[2] = f2tf32(Pr0[cc + 4]);
            pa0[3] = f2tf32(Pr0[8 * PPITCH + cc + 4]);
            pa1[0] = f2tf32(Pr1[cc]);
            pa1[1] = f2tf32(Pr1[8 * PPITCH + cc]);
            pa1[2] = f2tf32(Pr1[cc + 4]);
            pa1[3] = f2tf32(Pr1[8 * PPITCH + cc + 4]);
            unsigned bv[8][2];
            #pragma unroll
            for (int ni = 0; ni < 8; ni++) {
                const unsigned* p = Vs_ + (kc * 8 + tig) * VPITCH + ni * 8 + grp;
                bv[ni][0] = p[0];
                bv[ni][1] = p[4 * VPITCH];
            }
            #pragma unroll
            for (int ni = 0; ni < 8; ni++) {
                mma_tf32(acc_o[0][ni], pa0, bv[ni]);
                mma_tf32(acc_o[1][ni], pa1, bv[ni]);
            }
        }
        __syncwarp();
    }

    // ---- epilogue ----
    #pragma unroll
    for (int st = 0; st < 2; st++) {
        float il_lo = 1.0f / lrow[st*2+0];
        float il_hi = 1.0f / lrow[st*2+1];
        int qlo = qrow0 + st * 16;
        int qhi = qlo + 8;
        #pragma unroll
        for (int ni = 0; ni < 8; ni++) {
            int col = ni * 8 + 2 * tig;
            *(float2*)&Og[headoff + (size_t)qlo * DD + col] =
                make_float2(roundtf(acc_o[st][ni][0] * il_lo), roundtf(acc_o[st][ni][1] * il_lo));
            *(float2*)&Og[headoff + (size_t)qhi * DD + col] =
                make_float2(roundtf(acc_o[st][ni][2] * il_hi), roundtf(acc_o[st][ni][3] * il_hi));
        }
    }
}

// ---------------------------------------------------------------------------
extern "C" void kernel_launch(void* const* d_in, const int* in_sizes, int n_in,
                              void* d_out, int out_size)
{
    const float* x    = (const float*)d_in[0];
    const float* cosb = (const float*)d_in[1];
    const float* sinb = (const float*)d_in[2];
    const float* w_q  = (const float*)d_in[3];
    const float* w_k  = (const float*)d_in[4];
    const float* w_v  = (const float*)d_in[5];
    const float* w_o  = (const float*)d_in[6];
    float* out = (float*)d_out;

    float *q, *k, *v, *attn, *xr, *wr;
    cudaGetSymbolAddress((void**)&q,    g_q);
    cudaGetSymbolAddress((void**)&k,    g_k);
    cudaGetSymbolAddress((void**)&v,    g_v);
    cudaGetSymbolAddress((void**)&attn, g_attn);
    cudaGetSymbolAddress((void**)&xr,   g_xr);
    cudaGetSymbolAddress((void**)&wr,   g_wr);

    const int gm_smem = (2 * GA_TILE + 2 * GB_TILE) * sizeof(float);   // 110592
    cudaFuncSetAttribute(gemm_qkv_kernel,
                         cudaFuncAttributeMaxDynamicSharedMemorySize, gm_smem);
    cudaFuncSetAttribute(gemm_out_kernel,
                         cudaFuncAttributeMaxDynamicSharedMemorySize, gm_smem);

    const int fa_smem = (2 * KS_BUF + 2 * VS_BUF + 128 * PPITCH) * sizeof(float);
    cudaFuncSetAttribute(flash_attn_tc_kernel,
                         cudaFuncAttributeMaxDynamicSharedMemorySize, fa_smem);

    round_x_kernel<<<(MTOT * DD / 4) / 256, 256>>>(x, xr);
    round_w_kernel<<<(4 * DD * DD / 4) / 256, 256>>>(w_q, w_k, w_v, w_o, wr);

    dim3 qkvgrid(DD / 128, MTOT / 256, 3);   // (8, 32, 3)
    gemm_qkv_kernel<<<qkvgrid, 256, gm_smem>>>(xr, wr, q, k, v);

    int rope_threads = BB * TT * HH * 32;
    rope_kernel<<<rope_threads / 256, 256>>>(q, k, cosb, sinb);

    flash_attn_tc_kernel<<<dim3(TT / 128, BB * HH), 128, fa_smem>>>(q, k, v, attn);

    dim3 ogrid(DD / 128, MTOT / 256);        // (8, 32)
    gemm_out_kernel<<<ogrid, 256, gm_smem>>>(attn, wr + (size_t)3 * DD * DD, out);
}